// round 17
// baseline (speedup 1.0000x reference)
#include <cuda_runtime.h>
#include <cuda_bf16.h>
#include <cstdint>

// Problem constants
#define BATCH 32
#define N_ROI 2000
#define N_GT  100
#define N_LAB 21
#define K_POS 64
#define ROWS_PER_B (N_ROI * N_LAB)            // 42000
#define DELTA_FLOATS (BATCH * ROWS_PER_B * 4) // 5,376,000
#define TOTAL_ROWS (BATCH * ROWS_PER_B)       // 1,344,000 delta float4s (= label floats)
#define NROIS_ALL (BATCH * N_ROI)             // 64,000
#define RPB 64                                 // rois per iou block

// Writer tiling: one block handles BOTH outputs for 48 rois.
#define W_RPB 48
#define W_DV4 (W_RPB * N_LAB)                  // 1008 delta float4s per full tile
#define W_LV4 (W_RPB * N_LAB / 4)              // 252 label float4s per full tile
#define WBLK  ((NROIS_ALL + W_RPB - 1) / W_RPB)  // 1334

// Scratch (device globals; no runtime allocation)
__device__ unsigned int g_merged[BATCH * N_ROI];
__device__ int          g_maxidx[BATCH * N_ROI];
__device__ int          g_label [BATCH * N_ROI];   // gt label if positive, else -1
__device__ float4       g_delta [BATCH * N_ROI];   // valid only when positive

// ---------------------------------------------------------------------------
// Kernel A: per-roi max IoU + first-argmax over 100 gt boxes.
// IoU = inter/(S - inter) with S = bb_area + gt_area is increasing in
// inter/S, so the union subtraction leaves the loop. Tournament pairing:
// two independent candidates compete first (off the carried dependency
// chain), then ONE accumulator update per pair -> carried FSETP chain
// halves. First-index tie semantics preserved at every compare (strict >,
// lower index kept). Zero-overlap ties stay exact (0 > 0 false).
// ---------------------------------------------------------------------------
__global__ void __launch_bounds__(256) iou_kernel(const float4* __restrict__ roi,
                                                  const float4* __restrict__ gt)
{
    __shared__ float4 sg[N_GT];
    __shared__ float  sga[N_GT];
    const int b = blockIdx.y;
    const int t = threadIdx.x;

    if (t < N_GT) {
        const float4 g = gt[b * N_GT + t];
        sg[t]  = g;
        sga[t] = __fmul_rn(__fsub_rn(g.z, g.x), __fsub_rn(g.w, g.y));
    }
    __syncthreads();

    const int local = t >> 2;                 // 0..63 : roi within block
    const int seg   = t & 3;                  // 0..3  : gt segment
    const int n     = blockIdx.x * RPB + local;
    const int nc    = (n < N_ROI) ? n : (N_ROI - 1);   // clamp: no guard in loop

    const float4 q = roi[b * N_ROI + nc];
    const float by1 = q.x, bx1 = q.y, by2 = q.z, bx2 = q.w;
    const float bb_area = __fmul_rn(__fsub_rn(by2, by1), __fsub_rn(bx2, bx1));

    const int m0 = seg * 25;
    float aI = 0.0f, aS = 1.0f; int ai = m0;

#pragma unroll
    for (int i = 0; i < 12; ++i) {
        const int m1 = m0 + 2 * i;
        const int m2 = m1 + 1;
        const float4 g1 = sg[m1];
        const float4 g2 = sg[m2];

        const float iw1 = fmaxf(__fsub_rn(fminf(bx2, g1.w), fmaxf(bx1, g1.y)), 0.0f);
        const float ih1 = __fsub_rn(fminf(by2, g1.z), fmaxf(by1, g1.x));
        const float I1  = __fmul_rn(iw1, ih1);           // <=0 when no overlap
        const float S1  = __fadd_rn(bb_area, sga[m1]);   // > 0

        const float iw2 = fmaxf(__fsub_rn(fminf(bx2, g2.w), fmaxf(bx1, g2.y)), 0.0f);
        const float ih2 = __fsub_rn(fminf(by2, g2.z), fmaxf(by1, g2.x));
        const float I2  = __fmul_rn(iw2, ih2);
        const float S2  = __fadd_rn(bb_area, sga[m2]);

        // pairwise winner (independent of accumulator; strict > keeps m1 on tie)
        const bool  w2 = __fmul_rn(I2, S1) > __fmul_rn(I1, S2);
        const float wI = w2 ? I2 : I1;
        const float wS = w2 ? S2 : S1;
        const int   wm = w2 ? m2 : m1;

        // single accumulator update per pair (halved carried chain)
        if (__fmul_rn(wI, aS) > __fmul_rn(aI, wS)) { aI = wI; aS = wS; ai = wm; }
    }
    {   // leftover gt: m0 + 24
        const int m = m0 + 24;
        const float4 g = sg[m];
        const float iw = fmaxf(__fsub_rn(fminf(bx2, g.w), fmaxf(bx1, g.y)), 0.0f);
        const float ih = __fsub_rn(fminf(by2, g.z), fmaxf(by1, g.x));
        const float I  = __fmul_rn(iw, ih);
        const float S  = __fadd_rn(bb_area, sga[m]);
        if (__fmul_rn(I, aS) > __fmul_rn(aI, S)) { aI = I; aS = S; ai = m; }
    }

    // Reduce across the 4 lanes of this roi (lanes are consecutive in warp).
#pragma unroll
    for (int off = 1; off < 4; off <<= 1) {
        const float oI = __shfl_xor_sync(0xFFFFFFFFu, aI, off);
        const float oS = __shfl_xor_sync(0xFFFFFFFFu, aS, off);
        const int   oi = __shfl_xor_sync(0xFFFFFFFFu, ai, off);
        const float x = __fmul_rn(oI, aS);
        const float y = __fmul_rn(aI, oS);
        if (x > y || (x == y && oi < ai)) { aI = oI; aS = oS; ai = oi; }
    }

    if (seg == 0 && n < N_ROI) {
        const float best = (aI > 0.0f) ? __fdividef(aI, __fsub_rn(aS, aI)) : 0.0f;
        g_merged[b * N_ROI + n] = __float_as_uint(best);  // >=0 -> monotone bits
        g_maxidx[b * N_ROI + n] = ai;
    }
}

// ---------------------------------------------------------------------------
// Kernel B: per-batch top-64 selection (exact stable-sort semantics) and
// per-roi label/delta records. One block per batch, 1024 threads, 2 rois/thr.
// ---------------------------------------------------------------------------
__global__ void __launch_bounds__(1024) select_kernel(const float4* __restrict__ roi,
                                                      const float4* __restrict__ gt,
                                                      const int*    __restrict__ gtlab)
{
    __shared__ unsigned int hist[256];
    __shared__ unsigned int ssum[256];
    __shared__ unsigned int s_prefix, s_k;
    __shared__ int warp_sums[32];

    const int b = blockIdx.x;
    const int t = threadIdx.x;
    const int n0 = 2 * t, n1 = 2 * t + 1;
    const bool act = (n0 < N_ROI);
    const int lane = t & 31, wid = t >> 5;

    const unsigned int* gm = g_merged + b * N_ROI;
    unsigned v0 = 0u, v1 = 0u;
    if (act) { v0 = gm[n0]; v1 = gm[n1]; }
    if (t == 0) { s_prefix = 0u; s_k = K_POS; }
    __syncthreads();

#pragma unroll
    for (int pass = 0; pass < 4; ++pass) {
        const int shift = 24 - 8 * pass;
        if (t < 256) hist[t] = 0u;
        __syncthreads();
        const unsigned pfx = s_prefix;
        const unsigned kk0 = s_k;
        const unsigned hm = (pass == 0) ? 0u
                          : (0xFFFFFFFFu << ((shift + 8 > 31) ? 31 : shift + 8));
#pragma unroll
        for (int s = 0; s < 2; ++s) {
            const unsigned v = (s == 0) ? v0 : v1;
            unsigned key = 0x100u, bin = 0u;
            if (act && (v & hm) == (pfx & hm)) { bin = (v >> shift) & 255u; key = bin; }
            const unsigned mmask = __match_any_sync(0xFFFFFFFFu, key);
            if (key != 0x100u && lane == (__ffs(mmask) - 1))
                atomicAdd(&hist[bin], (unsigned)__popc(mmask));
        }
        __syncthreads();
        if (t < 32) {
            unsigned v[8], sum = 0u;
#pragma unroll
            for (int i = 0; i < 8; ++i) { v[i] = hist[t * 8 + i]; sum += v[i]; }
            unsigned suf = sum;
#pragma unroll
            for (int off = 1; off < 32; off <<= 1) {
                const unsigned x = __shfl_down_sync(0xFFFFFFFFu, suf, off);
                if (t + off < 32) suf += x;
            }
            unsigned acc = suf - sum;
#pragma unroll
            for (int i = 7; i >= 0; --i) { acc += v[i]; ssum[t * 8 + i] = acc; }
        }
        __syncthreads();
        if (t < 256) {
            const unsigned cum   = ssum[t];
            const unsigned above = (t < 255) ? ssum[t + 1] : 0u;
            if (cum >= kk0 && above < kk0) {
                s_prefix = pfx | ((unsigned)t << shift);
                s_k = kk0 - above;
            }
        }
        __syncthreads();
    }

    const unsigned T  = s_prefix;
    const unsigned kk = s_k;

    const int f0 = (act && v0 == T) ? 1 : 0;
    const int f1 = (act && v1 == T) ? 1 : 0;
    const int c  = f0 + f1;
    int inc = c;
#pragma unroll
    for (int off = 1; off < 32; off <<= 1) {
        const int x = __shfl_up_sync(0xFFFFFFFFu, inc, off);
        if (lane >= off) inc += x;
    }
    if (lane == 31) warp_sums[wid] = inc;
    __syncthreads();
    if (t < 32) {
        const int v = warp_sums[t];
        int iv = v;
#pragma unroll
        for (int off = 1; off < 32; off <<= 1) {
            const int x = __shfl_up_sync(0xFFFFFFFFu, iv, off);
            if (t >= off) iv += x;
        }
        warp_sums[t] = iv - v;
    }
    __syncthreads();
    const int excl = warp_sums[wid] + (inc - c);

    if (!act) return;

    const bool pos0 = (v0 > T) || (f0 && (unsigned)excl        < kk);
    const bool pos1 = (v1 > T) || (f1 && (unsigned)(excl + f0) < kk);

#pragma unroll
    for (int s = 0; s < 2; ++s) {
        const int n = (s == 0) ? n0 : n1;
        const bool pos = (s == 0) ? pos0 : pos1;
        const int gi = b * N_ROI + n;
        if (!pos) { g_label[gi] = -1; continue; }
        const int mi = g_maxidx[gi];
        const float4 q = roi[gi];
        const float4 g = gt[b * N_GT + mi];
        float bw = q.w - q.y;
        float bh = q.z - q.x;
        const float bcx = q.y + 0.5f * bw;
        const float bcy = q.x + 0.5f * bh;
        const float gw = g.w - g.y;
        const float gh = g.z - g.x;
        const float gcx = g.y + 0.5f * gw;
        const float gcy = g.x + 0.5f * gh;
        bw = (bw == 0.0f) ? 1e-3f : bw;
        bh = (bh == 0.0f) ? 1e-3f : bh;
        const float dx = (gw == 0.0f) ? 0.0f : (gcx - bcx) / bw;
        const float dy = (gh == 0.0f) ? 0.0f : (gcy - bcy) / bh;
        const float dw = (gw == 0.0f) ? 0.0f : logf(gw / bw);
        const float dh = (gh == 0.0f) ? 0.0f : logf(gh / bh);
        g_delta[gi] = make_float4(dy, dx, dh, dw);
        g_label[gi] = gtlab[b * N_GT + mi];
    }
}

// ---------------------------------------------------------------------------
// Kernel C: staged writer, one 48-roi tile per block covering BOTH outputs.
// Stage 48 labels + deltas in smem once, then write 1008 delta float4s and
// 252 label float4s (48*21 floats, exactly float4-aligned per tile; label
// float4s crossing a roi boundary stay inside the tile). No dependent
// global loads on the store path.
// ---------------------------------------------------------------------------
__global__ void __launch_bounds__(256) write_kernel(float4* __restrict__ out)
{
    __shared__ int    s_lab[W_RPB];
    __shared__ float4 s_del[W_RPB];

    const int t   = threadIdx.x;
    const int fr0 = blockIdx.x * W_RPB;
    const int cnt = (fr0 + W_RPB <= NROIS_ALL) ? W_RPB : (NROIS_ALL - fr0);

    if (t < cnt) {
        s_lab[t] = g_label[fr0 + t];
        s_del[t] = g_delta[fr0 + t];
    }
    __syncthreads();

    // ---- delta rows: cnt*21 float4s ----
    {
        const int nv = cnt * N_LAB;
        float4* dst = out + (size_t)fr0 * N_LAB;
#pragma unroll
        for (int k = 0; k < (W_DV4 + 255) / 256; ++k) {
            const int j = k * 256 + t;
            if (j < nv) {
                const int fr = j / N_LAB;     // 0..47 (const-div -> mulhi)
                const int l  = j - fr * N_LAB;
                const int lab = s_lab[fr];
                float4 dv = make_float4(0.f, 0.f, 0.f, 0.f);
                if (lab == l) dv = s_del[fr];
                dst[j] = dv;
            }
        }
    }

    // ---- label rows: cnt*21 floats = cnt*21/4 float4s (exactly aligned) ----
    {
        const int lv = cnt * N_LAB / 4;       // 252 full tile, 84 tail tile
        float4* dst = out + TOTAL_ROWS + ((size_t)fr0 * N_LAB) / 4;
#pragma unroll
        for (int k = 0; k < (W_LV4 + 255) / 256; ++k) {
            const int j = k * 256 + t;
            if (j < lv) {
                const int p  = j * 4;                 // tile-local label element
                const int r0 = p / N_LAB;             // 0..cnt-1
                const int l0 = p - r0 * N_LAB;
                const int laA = s_lab[r0];
                const int e0 = (laA < 0) ? 0 : laA;
                const int r1 = (r0 + 1 < cnt) ? r0 + 1 : r0;
                const int laB = s_lab[r1];
                const int e1 = (laB < 0) ? 0 : laB;
                float v[4];
#pragma unroll
                for (int kk = 0; kk < 4; ++kk) {
                    const int l = l0 + kk;
                    const bool second = (l >= N_LAB);
                    const int ll = second ? (l - N_LAB) : l;
                    const int ee = second ? e1 : e0;
                    v[kk] = (ll == ee) ? 1.0f : 0.0f;
                }
                dst[j] = make_float4(v[0], v[1], v[2], v[3]);
            }
        }
    }
}

// ---------------------------------------------------------------------------
extern "C" void kernel_launch(void* const* d_in, const int* in_sizes, int n_in,
                              void* d_out, int out_size)
{
    const float4* roi   = (const float4*)d_in[0];
    const float4* gt    = (const float4*)d_in[1];
    const int*    gtlab = (const int*)d_in[2];

    dim3 gA((N_ROI + RPB - 1) / RPB, BATCH);
    iou_kernel<<<gA, 256>>>(roi, gt);
    select_kernel<<<BATCH, 1024>>>(roi, gt, gtlab);
    write_kernel<<<WBLK, 256>>>((float4*)d_out);
}